// round 14
// baseline (speedup 1.0000x reference)
#include <cuda_runtime.h>
#include <stdint.h>

// ---------------------------------------------------------------------------
// Multires hash-grid encode (instant-NGP style), 2D, 16 levels, F=2.
// R13: 8-way warp-level split. Block = 256 thr = 8 warps, all covering the
// SAME 32 points; warp e handles levels {e, e+8}. Only 2 levels/thread ->
// all 8 corner gathers can be in flight at once (2x MLP vs R12).
// Levels 0-1 cached in smem; staged coalesced streaming output.
// ---------------------------------------------------------------------------

#define NUM_LEVELS   16
#define START_HASH   6
#define N_ENTRIES    524309ULL
#define PS1          19349663ULL

// floor(2^64 / 524309) (m odd => floor((2^64-1)/m) == floor(2^64/m))
#define MAGIC_M      (0xFFFFFFFFFFFFFFFFULL / N_ENTRIES)

#define PTS_PER_BLOCK 32
#define STRIDE        33            // padded row stride (floats) -> conflict-free
#define SMTAB_ENTRIES 1378          // levels 0 (289) + 1 (1089)

__device__ __constant__ int c_off[NUM_LEVELS] =
    {0,289,1378,5603,22244,88293,351462,875771,
     1400080,1924389,2448698,2973007,3497316,4021625,4545934,5070243};

__device__ __forceinline__ int mod_prime(unsigned long long h) {
    unsigned long long q = __umul64hi(h, MAGIC_M);
    unsigned long long r = h - q * N_ENTRIES;
    if (r >= N_ENTRIES) r -= N_ENTRIES;
    return (int)r;
}

__device__ __forceinline__ void corners(float px, float py, int l,
                                        int& x0, int& y0, int& x1, int& y1,
                                        float& tx, float& ty) {
    const float scale = (float)(16 << l);
    const float fx = px * scale;
    const float fy = py * scale;
    // Match reference exactly: trunc fp32; hi corner = trunc(fx+1.0f)
    x0 = (int)fx;  y0 = (int)fy;
    x1 = (int)(fx + 1.0f);  y1 = (int)(fy + 1.0f);
    tx = fx - (float)x0;    // exact: fx < 2^23
    ty = fy - (float)y0;
}

__device__ __forceinline__ void hash4(int x0, int y0, int x1, int y1, int off,
                                      int& i00, int& i01, int& i10, int& i11) {
    const unsigned long long hy0 = (unsigned long long)(unsigned)y0 * PS1;
    const unsigned long long hy1 = (unsigned long long)(unsigned)y1 * PS1;
    const unsigned long long ux0 = (unsigned)x0;
    const unsigned long long ux1 = (unsigned)x1;
    i00 = mod_prime(ux0 ^ hy0) + off;
    i01 = mod_prime(ux0 ^ hy1) + off;
    i10 = mod_prime(ux1 ^ hy0) + off;
    i11 = mod_prime(ux1 ^ hy1) + off;
}

__device__ __forceinline__ void bilerp(float tx, float ty,
                                       float2 v00, float2 v01, float2 v10, float2 v11,
                                       float& f0, float& f1) {
    const float wx0 = 1.0f - tx, wx1 = tx;
    const float wy0 = 1.0f - ty, wy1 = ty;
    const float w00 = wx0 * wy0, w01 = wx0 * wy1;
    const float w10 = wx1 * wy0, w11 = wx1 * wy1;
    f0 = w00 * v00.x;
    f0 = fmaf(w01, v01.x, f0);
    f0 = fmaf(w10, v10.x, f0);
    f0 = fmaf(w11, v11.x, f0);
    f1 = w00 * v00.y;
    f1 = fmaf(w01, v01.y, f1);
    f1 = fmaf(w10, v10.y, f1);
    f1 = fmaf(w11, v11.y, f1);
}

__global__ __launch_bounds__(256, 7) void hashgrid_kernel(
    const float* __restrict__ x,      // [N,2]
    const float* __restrict__ data,   // [TABLE_SIZE,2]
    float* __restrict__ out,          // [N,32]
    int n)
{
    __shared__ __align__(16) float2 smtab[SMTAB_ENTRIES];          // 11024 B
    __shared__ __align__(16) float  stage[PTS_PER_BLOCK * STRIDE]; //  4224 B

    const int tid  = threadIdx.x;
    const int e    = tid >> 5;        // warp id = level residue (0..7)
    const int lane = tid & 31;        // point index within block

    const int blockStart = blockIdx.x * PTS_PER_BLOCK;
    const int pt = blockStart + lane;

    const float2* __restrict__ tab = reinterpret_cast<const float2*>(data);

    // cooperative fill of level 0-1 tables (coalesced)
    for (int t = tid; t < SMTAB_ENTRIES; t += 256)
        smtab[t] = __ldg(&tab[t]);
    __syncthreads();

    if (pt < n) {
        const float2 p = reinterpret_cast<const float2*>(x)[pt];
        float* srow = &stage[lane * STRIDE];

        const int lA = e;             // level A: 0..7
        const int lB = e + 8;         // level B: 8..15 (always hash)

        // ---- indices for both levels, computed up front ----
        int ax0, ay0, ax1, ay1;  float atx, aty;
        int bx0, by0, bx1, by1;  float btx, bty;
        corners(p.x, p.y, lA, ax0, ay0, ax1, ay1, atx, aty);
        corners(p.x, p.y, lB, bx0, by0, bx1, by1, btx, bty);

        int iB00, iB01, iB10, iB11;
        hash4(bx0, by0, bx1, by1, c_off[lB], iB00, iB01, iB10, iB11);

        int iA00, iA01, iA10, iA11;
        if (e >= 6) {
            hash4(ax0, ay0, ax1, ay1, c_off[lA], iA00, iA01, iA10, iA11);
        } else {
            const int r1  = (16 << lA) + 1;
            const int off = c_off[lA];
            const int a0  = ax0 * r1 + off;
            const int a1  = ax1 * r1 + off;
            iA00 = a0 + ay0;  iA01 = a0 + ay1;
            iA10 = a1 + ay0;  iA11 = a1 + ay1;
        }

        // ---- issue all 8 gathers back-to-back (max MLP) ----
        const float2 b00 = __ldg(&tab[iB00]);
        const float2 b01 = __ldg(&tab[iB01]);
        const float2 b10 = __ldg(&tab[iB10]);
        const float2 b11 = __ldg(&tab[iB11]);

        float2 a00, a01, a10, a11;
        if (e < 2) {            // levels 0,1 from smem
            a00 = smtab[iA00];  a01 = smtab[iA01];
            a10 = smtab[iA10];  a11 = smtab[iA11];
        } else {
            a00 = __ldg(&tab[iA00]);
            a01 = __ldg(&tab[iA01]);
            a10 = __ldg(&tab[iA10]);
            a11 = __ldg(&tab[iA11]);
        }

        // ---- interpolate + write to staging smem ----
        float fA0, fA1, fB0, fB1;
        bilerp(atx, aty, a00, a01, a10, a11, fA0, fA1);
        bilerp(btx, bty, b00, b01, b10, b11, fB0, fB1);

        srow[(lA << 1)]     = fA0;
        srow[(lA << 1) + 1] = fA1;
        srow[(lB << 1)]     = fB0;
        srow[(lB << 1) + 1] = fB1;
    }
    __syncthreads();

    // coalesced streaming stores: 32 pts * 32 floats = 1024 floats / block
    const size_t outBase = (size_t)blockStart * 32;
    int limit = PTS_PER_BLOCK * 32;
    if (blockStart + PTS_PER_BLOCK > n) {
        limit = (n - blockStart) * 32;
        if (limit < 0) limit = 0;
    }
    #pragma unroll
    for (int idx = tid; idx < limit; idx += 256) {
        const int pp = idx >> 5;
        const int j  = idx & 31;
        __stcs(&out[outBase + idx], stage[pp * STRIDE + j]);
    }
}

extern "C" void kernel_launch(void* const* d_in, const int* in_sizes, int n_in,
                              void* d_out, int out_size) {
    const float* x    = (const float*)d_in[0];   // [N,2] fp32
    const float* data = (const float*)d_in[1];   // [TABLE_SIZE,2] fp32
    float* out        = (float*)d_out;           // [N,32] fp32

    const int n = in_sizes[0] / 2;               // number of points
    const int blocks = (n + PTS_PER_BLOCK - 1) / PTS_PER_BLOCK;
    hashgrid_kernel<<<blocks, 256>>>(x, data, out, n);
}

// round 15
// speedup vs baseline: 1.1302x; 1.1302x over previous
#include <cuda_runtime.h>
#include <stdint.h>

// ---------------------------------------------------------------------------
// Multires hash-grid encode (instant-NGP style), 2D, 16 levels, F=2.
// R14: R12 structure (4-way warp-level split over 64 pts/block, L0-1 smem
// cache, staged coalesced output) + pairwise level batching: levels processed
// in 2 batches of 2; all 8 corner gathers of a batch issued back-to-back
// (MLP 8/thread vs 4). launch_bounds(256,6) -> 40 regs, 48 warps/SM.
// ---------------------------------------------------------------------------

#define NUM_LEVELS   16
#define START_HASH   6
#define N_ENTRIES    524309ULL
#define PS1          19349663ULL

// floor(2^64 / 524309) (m odd => floor((2^64-1)/m) == floor(2^64/m))
#define MAGIC_M      (0xFFFFFFFFFFFFFFFFULL / N_ENTRIES)

#define PTS_PER_BLOCK 64
#define STRIDE        33            // padded row stride (floats) -> conflict-free
#define SMTAB_ENTRIES 1378          // levels 0 (289) + 1 (1089)

__device__ __constant__ int c_off[NUM_LEVELS] =
    {0,289,1378,5603,22244,88293,351462,875771,
     1400080,1924389,2448698,2973007,3497316,4021625,4545934,5070243};

__device__ __forceinline__ int mod_prime(unsigned long long h) {
    unsigned long long q = __umul64hi(h, MAGIC_M);
    unsigned long long r = h - q * N_ENTRIES;
    if (r >= N_ENTRIES) r -= N_ENTRIES;
    return (int)r;
}

__device__ __forceinline__ void corners(float px, float py, int l,
                                        int& x0, int& y0, int& x1, int& y1,
                                        float& tx, float& ty) {
    const float scale = (float)(16 << l);
    const float fx = px * scale;
    const float fy = py * scale;
    // Match reference exactly: trunc fp32; hi corner = trunc(fx+1.0f)
    x0 = (int)fx;  y0 = (int)fy;
    x1 = (int)(fx + 1.0f);  y1 = (int)(fy + 1.0f);
    tx = fx - (float)x0;    // exact: fx < 2^23
    ty = fy - (float)y0;
}

__device__ __forceinline__ void hash4(int x0, int y0, int x1, int y1, int off,
                                      int& i00, int& i01, int& i10, int& i11) {
    const unsigned long long hy0 = (unsigned long long)(unsigned)y0 * PS1;
    const unsigned long long hy1 = (unsigned long long)(unsigned)y1 * PS1;
    const unsigned long long ux0 = (unsigned)x0;
    const unsigned long long ux1 = (unsigned)x1;
    i00 = mod_prime(ux0 ^ hy0) + off;
    i01 = mod_prime(ux0 ^ hy1) + off;
    i10 = mod_prime(ux1 ^ hy0) + off;
    i11 = mod_prime(ux1 ^ hy1) + off;
}

__device__ __forceinline__ void grid4(int x0, int y0, int x1, int y1,
                                      int r1, int off,
                                      int& i00, int& i01, int& i10, int& i11) {
    const int a0 = x0 * r1 + off;
    const int a1 = x1 * r1 + off;
    i00 = a0 + y0;  i01 = a0 + y1;
    i10 = a1 + y0;  i11 = a1 + y1;
}

__device__ __forceinline__ void bilerp(float tx, float ty,
                                       float2 v00, float2 v01, float2 v10, float2 v11,
                                       float& f0, float& f1) {
    const float wx0 = 1.0f - tx, wx1 = tx;
    const float wy0 = 1.0f - ty, wy1 = ty;
    const float w00 = wx0 * wy0, w01 = wx0 * wy1;
    const float w10 = wx1 * wy0, w11 = wx1 * wy1;
    f0 = w00 * v00.x;
    f0 = fmaf(w01, v01.x, f0);
    f0 = fmaf(w10, v10.x, f0);
    f0 = fmaf(w11, v11.x, f0);
    f1 = w00 * v00.y;
    f1 = fmaf(w01, v01.y, f1);
    f1 = fmaf(w10, v10.y, f1);
    f1 = fmaf(w11, v11.y, f1);
}

__global__ __launch_bounds__(256, 6) void hashgrid_kernel(
    const float* __restrict__ x,      // [N,2]
    const float* __restrict__ data,   // [TABLE_SIZE,2]
    float* __restrict__ out,          // [N,32]
    int n)
{
    __shared__ __align__(16) float2 smtab[SMTAB_ENTRIES];          // 11024 B
    __shared__ __align__(16) float  stage[PTS_PER_BLOCK * STRIDE]; //  8448 B

    const int tid  = threadIdx.x;
    const int warp = tid >> 5;
    const int lane = tid & 31;
    const int e    = warp & 3;                  // level residue this warp handles
    const int pw   = ((warp >> 2) << 5) + lane; // point index within block 0..63

    const int blockStart = blockIdx.x * PTS_PER_BLOCK;
    const int pt = blockStart + pw;

    const float2* __restrict__ tab = reinterpret_cast<const float2*>(data);

    // cooperative fill of level 0-1 tables (coalesced)
    for (int t = tid; t < SMTAB_ENTRIES; t += 256)
        smtab[t] = __ldg(&tab[t]);
    __syncthreads();

    if (pt < n) {
        const float2 p = reinterpret_cast<const float2*>(x)[pt];
        float* srow = &stage[pw * STRIDE];

        // ================= Batch 0: levels lA=e (0-3), lB=e+4 (4-7) =========
        {
            const int lA = e, lB = e + 4;
            int ax0, ay0, ax1, ay1;  float atx, aty;
            int bx0, by0, bx1, by1;  float btx, bty;
            corners(p.x, p.y, lA, ax0, ay0, ax1, ay1, atx, aty);
            corners(p.x, p.y, lB, bx0, by0, bx1, by1, btx, bty);

            int iA00, iA01, iA10, iA11;
            int iB00, iB01, iB10, iB11;
            // A: levels 0-3 are always dense grid (smem for e<2)
            grid4(ax0, ay0, ax1, ay1, (16 << lA) + 1, c_off[lA],
                  iA00, iA01, iA10, iA11);
            // B: levels 4,5 grid (e<2); levels 6,7 hash (e>=2). Warp-uniform.
            if (e < 2) {
                grid4(bx0, by0, bx1, by1, (16 << lB) + 1, c_off[lB],
                      iB00, iB01, iB10, iB11);
            } else {
                hash4(bx0, by0, bx1, by1, c_off[lB], iB00, iB01, iB10, iB11);
            }

            // issue all global gathers back-to-back
            const float2 b00 = __ldg(&tab[iB00]);
            const float2 b01 = __ldg(&tab[iB01]);
            const float2 b10 = __ldg(&tab[iB10]);
            const float2 b11 = __ldg(&tab[iB11]);

            float2 a00, a01, a10, a11;
            if (e < 2) {        // levels 0,1 from smem
                a00 = smtab[iA00];  a01 = smtab[iA01];
                a10 = smtab[iA10];  a11 = smtab[iA11];
            } else {            // levels 2,3 from global
                a00 = __ldg(&tab[iA00]);
                a01 = __ldg(&tab[iA01]);
                a10 = __ldg(&tab[iA10]);
                a11 = __ldg(&tab[iA11]);
            }

            float fA0, fA1, fB0, fB1;
            bilerp(atx, aty, a00, a01, a10, a11, fA0, fA1);
            bilerp(btx, bty, b00, b01, b10, b11, fB0, fB1);
            srow[(lA << 1)]     = fA0;
            srow[(lA << 1) + 1] = fA1;
            srow[(lB << 1)]     = fB0;
            srow[(lB << 1) + 1] = fB1;
        }

        // ================= Batch 1: levels lA=e+8, lB=e+12 (all hash) =======
        {
            const int lA = e + 8, lB = e + 12;
            int ax0, ay0, ax1, ay1;  float atx, aty;
            int bx0, by0, bx1, by1;  float btx, bty;
            corners(p.x, p.y, lA, ax0, ay0, ax1, ay1, atx, aty);
            corners(p.x, p.y, lB, bx0, by0, bx1, by1, btx, bty);

            int iA00, iA01, iA10, iA11;
            int iB00, iB01, iB10, iB11;
            hash4(ax0, ay0, ax1, ay1, c_off[lA], iA00, iA01, iA10, iA11);
            hash4(bx0, by0, bx1, by1, c_off[lB], iB00, iB01, iB10, iB11);

            // 8 gathers in flight
            const float2 a00 = __ldg(&tab[iA00]);
            const float2 a01 = __ldg(&tab[iA01]);
            const float2 a10 = __ldg(&tab[iA10]);
            const float2 a11 = __ldg(&tab[iA11]);
            const float2 b00 = __ldg(&tab[iB00]);
            const float2 b01 = __ldg(&tab[iB01]);
            const float2 b10 = __ldg(&tab[iB10]);
            const float2 b11 = __ldg(&tab[iB11]);

            float fA0, fA1, fB0, fB1;
            bilerp(atx, aty, a00, a01, a10, a11, fA0, fA1);
            bilerp(btx, bty, b00, b01, b10, b11, fB0, fB1);
            srow[(lA << 1)]     = fA0;
            srow[(lA << 1) + 1] = fA1;
            srow[(lB << 1)]     = fB0;
            srow[(lB << 1) + 1] = fB1;
        }
    }
    __syncthreads();

    // coalesced streaming stores: 64 pts * 32 floats = 2048 floats / block
    const size_t outBase = (size_t)blockStart * 32;
    int limit = PTS_PER_BLOCK * 32;
    if (blockStart + PTS_PER_BLOCK > n) {
        limit = (n - blockStart) * 32;
        if (limit < 0) limit = 0;
    }
    #pragma unroll
    for (int idx = tid; idx < limit; idx += 256) {
        const int pp = idx >> 5;
        const int j  = idx & 31;
        __stcs(&out[outBase + idx], stage[pp * STRIDE + j]);
    }
}

extern "C" void kernel_launch(void* const* d_in, const int* in_sizes, int n_in,
                              void* d_out, int out_size) {
    const float* x    = (const float*)d_in[0];   // [N,2] fp32
    const float* data = (const float*)d_in[1];   // [TABLE_SIZE,2] fp32
    float* out        = (float*)d_out;           // [N,32] fp32

    const int n = in_sizes[0] / 2;               // number of points
    const int blocks = (n + PTS_PER_BLOCK - 1) / PTS_PER_BLOCK;
    hashgrid_kernel<<<blocks, 256>>>(x, data, out, n);
}

// round 17
// speedup vs baseline: 1.1509x; 1.0183x over previous
#include <cuda_runtime.h>
#include <stdint.h>

// ---------------------------------------------------------------------------
// Multires hash-grid encode (instant-NGP style), 2D, 16 levels, F=2.
// R15: R12 inner loop, scaled to 1024-thread CTAs (2 CTAs/SM, 64 warps/SM).
// Levels 0-2 tables (5603 entries, 44.8KB) cached in dynamic smem; 256 pts
// per block -> fill cost amortized 4x vs R12. 4-way warp-level split, padded
// smem staging + coalesced streaming stores. <=32 regs via launch_bounds.
// ---------------------------------------------------------------------------

#define NUM_LEVELS   16
#define START_HASH   6
#define N_ENTRIES    524309ULL
#define PS1          19349663ULL

// floor(2^64 / 524309) (m odd => floor((2^64-1)/m) == floor(2^64/m))
#define MAGIC_M      (0xFFFFFFFFFFFFFFFFULL / N_ENTRIES)

#define THREADS       1024
#define PTS_PER_BLOCK 256
#define STRIDE        33            // padded row stride (floats) -> conflict-free
#define SMTAB_ENTRIES 5603          // levels 0 (289) + 1 (1089) + 2 (4225)

// dynamic smem layout: [smtab float2 x 5603 | stage float x 256*33]
#define SMTAB_BYTES   (SMTAB_ENTRIES * 8)                  // 44824
#define STAGE_FLOATS  (PTS_PER_BLOCK * STRIDE)             // 8448
#define SMEM_TOTAL    (SMTAB_BYTES + STAGE_FLOATS * 4)     // 78616

__device__ __constant__ int c_off[NUM_LEVELS] =
    {0,289,1378,5603,22244,88293,351462,875771,
     1400080,1924389,2448698,2973007,3497316,4021625,4545934,5070243};

__device__ __forceinline__ int mod_prime(unsigned long long h) {
    unsigned long long q = __umul64hi(h, MAGIC_M);
    unsigned long long r = h - q * N_ENTRIES;
    if (r >= N_ENTRIES) r -= N_ENTRIES;
    return (int)r;
}

__global__ __launch_bounds__(THREADS, 2) void hashgrid_kernel(
    const float* __restrict__ x,      // [N,2]
    const float* __restrict__ data,   // [TABLE_SIZE,2]
    float* __restrict__ out,          // [N,32]
    int n)
{
    extern __shared__ __align__(16) char dynsmem[];
    float2* smtab = reinterpret_cast<float2*>(dynsmem);
    float*  stage = reinterpret_cast<float*>(dynsmem + SMTAB_BYTES);

    const int tid  = threadIdx.x;
    const int warp = tid >> 5;
    const int lane = tid & 31;
    const int e    = warp & 3;                  // level residue this warp handles
    const int pw   = ((warp >> 2) << 5) + lane; // point index within block 0..255

    const int blockStart = blockIdx.x * PTS_PER_BLOCK;
    const int pt = blockStart + pw;

    const float2* __restrict__ tab = reinterpret_cast<const float2*>(data);

    // cooperative fill of level 0-2 tables (coalesced)
    for (int t = tid; t < SMTAB_ENTRIES; t += THREADS)
        smtab[t] = __ldg(&tab[t]);
    __syncthreads();

    if (pt < n) {
        const float2 p = reinterpret_cast<const float2*>(x)[pt];
        float* srow = &stage[pw * STRIDE];

        #pragma unroll
        for (int k = 0; k < 4; ++k) {
            // level l = 4k + e   (e is warp-uniform runtime 0..3)
            const int l   = (k << 2) + e;
            const int res = 16 << l;
            const float scale = (float)res;
            const float fx = p.x * scale;
            const float fy = p.y * scale;

            // Match reference exactly: trunc fp32; hi corner = trunc(fx+1.0f)
            const int x0 = (int)fx;
            const int y0 = (int)fy;
            const int x1 = (int)(fx + 1.0f);
            const int y1 = (int)(fy + 1.0f);

            const float tx = fx - (float)x0;   // exact: fx < 2^23
            const float ty = fy - (float)y0;

            float2 v00, v01, v10, v11;
            // All branches warp-uniform; no lane divergence anywhere.
            if (k == 0 && e < 3) {
                // levels 0,1,2: smem-cached dense grid (global layout offsets)
                const int r1  = res + 1;
                const int a0  = x0 * r1 + c_off[l];
                const int a1  = x1 * r1 + c_off[l];
                v00 = smtab[a0 + y0];
                v01 = smtab[a0 + y1];
                v10 = smtab[a1 + y0];
                v11 = smtab[a1 + y1];
            } else if (k == 0 || (k == 1 && e < 2)) {
                // levels 3,4,5: dense grid from global
                const int r1  = res + 1;
                const int off = c_off[l];
                const int a0  = x0 * r1 + off;
                const int a1  = x1 * r1 + off;
                v00 = __ldg(&tab[a0 + y0]);
                v01 = __ldg(&tab[a0 + y1]);
                v10 = __ldg(&tab[a1 + y0]);
                v11 = __ldg(&tab[a1 + y1]);
            } else {
                // levels 6..15: spatial hash
                const unsigned long long hy0 = (unsigned long long)(unsigned)y0 * PS1;
                const unsigned long long hy1 = (unsigned long long)(unsigned)y1 * PS1;
                const unsigned long long ux0 = (unsigned)x0;
                const unsigned long long ux1 = (unsigned)x1;
                const int off = c_off[l];
                const int i00 = mod_prime(ux0 ^ hy0) + off;
                const int i01 = mod_prime(ux0 ^ hy1) + off;
                const int i10 = mod_prime(ux1 ^ hy0) + off;
                const int i11 = mod_prime(ux1 ^ hy1) + off;
                v00 = __ldg(&tab[i00]);
                v01 = __ldg(&tab[i01]);
                v10 = __ldg(&tab[i10]);
                v11 = __ldg(&tab[i11]);
            }

            const float wx0 = 1.0f - tx, wx1 = tx;
            const float wy0 = 1.0f - ty, wy1 = ty;
            const float w00 = wx0 * wy0;
            const float w01 = wx0 * wy1;
            const float w10 = wx1 * wy0;
            const float w11 = wx1 * wy1;

            float f0 = w00 * v00.x;
            f0 = fmaf(w01, v01.x, f0);
            f0 = fmaf(w10, v10.x, f0);
            f0 = fmaf(w11, v11.x, f0);
            float f1 = w00 * v00.y;
            f1 = fmaf(w01, v01.y, f1);
            f1 = fmaf(w10, v10.y, f1);
            f1 = fmaf(w11, v11.y, f1);

            // straight to staging smem (no acc array -> low reg pressure)
            srow[(l << 1)]     = f0;
            srow[(l << 1) + 1] = f1;
        }
    }
    __syncthreads();

    // coalesced streaming stores: 256 pts * 32 floats = 8192 floats / block
    const size_t outBase = (size_t)blockStart * 32;
    int limit = PTS_PER_BLOCK * 32;
    if (blockStart + PTS_PER_BLOCK > n) {
        limit = (n - blockStart) * 32;
        if (limit < 0) limit = 0;
    }
    #pragma unroll
    for (int idx = tid; idx < limit; idx += THREADS) {
        const int pp = idx >> 5;
        const int j  = idx & 31;
        __stcs(&out[outBase + idx], stage[pp * STRIDE + j]);
    }
}

extern "C" void kernel_launch(void* const* d_in, const int* in_sizes, int n_in,
                              void* d_out, int out_size) {
    const float* x    = (const float*)d_in[0];   // [N,2] fp32
    const float* data = (const float*)d_in[1];   // [TABLE_SIZE,2] fp32
    float* out        = (float*)d_out;           // [N,32] fp32

    cudaFuncSetAttribute(hashgrid_kernel,
                         cudaFuncAttributeMaxDynamicSharedMemorySize, SMEM_TOTAL);

    const int n = in_sizes[0] / 2;               // number of points
    const int blocks = (n + PTS_PER_BLOCK - 1) / PTS_PER_BLOCK;
    hashgrid_kernel<<<blocks, THREADS, SMEM_TOTAL>>>(x, data, out, n);
}